// round 4
// baseline (speedup 1.0000x reference)
#include <cuda_runtime.h>
#include <cuda_fp16.h>
#include <cstdint>

#define BB 8
#define TT 256
#define UU 64
#define ENC_DIM 512
#define PRED_DIM 640
#define JDIM 512
#define VOCAB 1024
#define MROWS (BB * TT * UU)   // 131072

// ---------------------------------------------------------------------------
// Device scratch
// ---------------------------------------------------------------------------
__device__ float g_enc_p[BB * TT * JDIM];            // 4 MB
__device__ float g_pred_p[BB * UU * JDIM];           // 1 MB
__device__ __half g_a[(size_t)MROWS * JDIM];         // 128 MB (single fp16 plane)
__device__ __half g_wt_hi[VOCAB * JDIM];             // 1 MB  (W^T fp16 hi)
__device__ __half g_wt_lo[VOCAB * JDIM];             // 1 MB  (W^T fp16 lo)

// ---------------------------------------------------------------------------
// Helpers
// ---------------------------------------------------------------------------
__device__ __forceinline__ uint32_t smem_u32(const void* p) {
    uint32_t a;
    asm("{ .reg .u64 t; cvta.to.shared.u64 t, %1; cvt.u32.u64 %0, t; }" : "=r"(a) : "l"(p));
    return a;
}
#define CP16(dst, src) \
    asm volatile("cp.async.cg.shared.global [%0], [%1], 16;" :: "r"((uint32_t)(dst)), "l"(src) : "memory")
#define CP_COMMIT() asm volatile("cp.async.commit_group;" ::: "memory")

#define LDSM4(r, addr) \
    asm volatile("ldmatrix.sync.aligned.m8n8.x4.shared.b16 {%0,%1,%2,%3}, [%4];" \
                 : "=r"((r)[0]), "=r"((r)[1]), "=r"((r)[2]), "=r"((r)[3]) : "r"(addr))

#define MMA16816(acc, a, b0, b1) \
    asm volatile("mma.sync.aligned.m16n8k16.row.col.f32.f16.f16.f32 " \
                 "{%0,%1,%2,%3},{%4,%5,%6,%7},{%8,%9},{%0,%1,%2,%3};" \
                 : "+f"((acc)[0]), "+f"((acc)[1]), "+f"((acc)[2]), "+f"((acc)[3]) \
                 : "r"((a)[0]), "r"((a)[1]), "r"((a)[2]), "r"((a)[3]), "r"(b0), "r"(b1))

// Accurate tanh (independent of fast-math): sign(x)*(1-e)/(1+e), e = exp(-2|x|)
__device__ __forceinline__ float tanh_f(float x) {
    float ax = fabsf(x);
    float e  = __expf(-2.0f * ax);
    float t  = (1.0f - e) / (1.0f + e);
    return (x < 0.0f) ? -t : t;
}
__device__ __forceinline__ uint32_t pack2h(__half a, __half b) {
    return (uint32_t)__half_as_ushort(a) | ((uint32_t)__half_as_ushort(b) << 16);
}

// ---------------------------------------------------------------------------
// Projection GEMM (fp32 SIMT): C[M, 512] = A[M, K] @ W[K, 512] + bias
// ---------------------------------------------------------------------------
template <int K, int WHICH>
__global__ __launch_bounds__(256) void proj_kernel(
    const float* __restrict__ A, const float* __restrict__ W, const float* __restrict__ bias)
{
    __shared__ float As[16][68];
    __shared__ float Bs[16][128];
    float* __restrict__ C = (WHICH == 0) ? g_enc_p : g_pred_p;
    const int N = JDIM;
    const int tid = threadIdx.x;
    const int ty = tid >> 4, tx = tid & 15;
    const int m0 = blockIdx.y * 64, n0 = blockIdx.x * 128;
    const int lm = tid >> 2, lk = (tid & 3) << 2;

    float acc[4][8];
#pragma unroll
    for (int i = 0; i < 4; i++)
#pragma unroll
        for (int j = 0; j < 8; j++) acc[i][j] = 0.0f;

    for (int k0 = 0; k0 < K; k0 += 16) {
        float4 a4 = *(const float4*)&A[(m0 + lm) * K + k0 + lk];
        As[lk + 0][lm] = a4.x; As[lk + 1][lm] = a4.y;
        As[lk + 2][lm] = a4.z; As[lk + 3][lm] = a4.w;
#pragma unroll
        for (int r = 0; r < 2; r++) {
            int f = tid + r * 256;
            int kk = f >> 5, nn = (f & 31) << 2;
            *(float4*)&Bs[kk][nn] = *(const float4*)&W[(k0 + kk) * N + n0 + nn];
        }
        __syncthreads();
#pragma unroll
        for (int k = 0; k < 16; k++) {
            float4 av = *(const float4*)&As[k][ty << 2];
            float a[4] = {av.x, av.y, av.z, av.w};
            float bb[8];
#pragma unroll
            for (int j = 0; j < 8; j++) bb[j] = Bs[k][tx + (j << 4)];
#pragma unroll
            for (int i = 0; i < 4; i++)
#pragma unroll
                for (int j = 0; j < 8; j++) acc[i][j] = fmaf(a[i], bb[j], acc[i][j]);
        }
        __syncthreads();
    }
#pragma unroll
    for (int j = 0; j < 8; j++) {
        float bj = bias[n0 + tx + (j << 4)];
#pragma unroll
        for (int i = 0; i < 4; i++)
            C[(m0 + (ty << 2) + i) * N + n0 + tx + (j << 4)] = acc[i][j] + bj;
    }
}

// ---------------------------------------------------------------------------
// prep_W: Wt[v,k] = split(W_joint[k,v]) into fp16 hi/lo planes (B exact)
// ---------------------------------------------------------------------------
__global__ __launch_bounds__(256) void prep_w_kernel(const float* __restrict__ W) {
    int gid = blockIdx.x * 256 + threadIdx.x;       // 0 .. 524287
    int v = gid >> 9, k = gid & 511;
    float w = W[k * VOCAB + v];
    __half hi = __float2half_rn(w);
    __half lo = __float2half_rn(w - __half2float(hi));
    g_wt_hi[gid] = hi;
    g_wt_lo[gid] = lo;
}

// ---------------------------------------------------------------------------
// prep_A: A[m,k] = fp16(tanh(enc_p[bt,k] + pred_p[b,u,k]))
// ---------------------------------------------------------------------------
__global__ __launch_bounds__(256) void prep_a_kernel() {
    int gid = blockIdx.x * 256 + threadIdx.x;       // 0 .. 8388607
    int m  = gid >> 6;
    int k8 = (gid & 63) << 3;
    int bt = m >> 6;
    int b  = bt >> 8;
    int u  = m & 63;
    const float4* e = (const float4*)(g_enc_p + (size_t)bt * JDIM + k8);
    const float4* p = (const float4*)(g_pred_p + ((size_t)(b * UU + u)) * JDIM + k8);

    __half h[8];
#pragma unroll
    for (int q = 0; q < 2; q++) {
        float4 ev = e[q], pv = p[q];
        float v[4] = {ev.x + pv.x, ev.y + pv.y, ev.z + pv.z, ev.w + pv.w};
#pragma unroll
        for (int i = 0; i < 4; i++)
            h[q * 4 + i] = __float2half_rn(tanh_f(v[i]));
    }
    uint4 H;
    H.x = pack2h(h[0], h[1]); H.y = pack2h(h[2], h[3]);
    H.z = pack2h(h[4], h[5]); H.w = pack2h(h[6], h[7]);
    *(uint4*)(g_a + (size_t)m * JDIM + k8) = H;
}

// ---------------------------------------------------------------------------
// Joint GEMM via mma.sync (HMMA): C = A_fp16 @ (Wt_hi + Wt_lo)^T + bias
// BM=128, BN=256, BK=32, 256 threads (8 warps 2x4), warp tile 64x64.
// 3-stage cp.async pipeline. 2 fp16 passes: A*B_hi, A*B_lo.
// ---------------------------------------------------------------------------
#define BM 128
#define BN 256
#define BK 32
#define NSTG 16                         // 512 / 32
#define ASTRIDE 80                      // 32 fp16 = 64B data, padded to 80B
#define A_PLANE (BM * ASTRIDE)          // 10240
#define B_PLANE (BN * ASTRIDE)          // 20480
#define STG_BYTES (A_PLANE + 2 * B_PLANE)      // 51200
#define OFF_A   0
#define OFF_BHI A_PLANE
#define OFF_BLO (A_PLANE + B_PLANE)
#define JOINT_SMEM (3 * STG_BYTES + 1024)      // + bias

__device__ __forceinline__ void load_stage(uint32_t sbase, int k0, int m0, int n0, int tid) {
#pragma unroll
    for (int it = 0; it < 2; it++) {
        int c = tid + it * 256;            // 0..511
        int row = c >> 2, cq = c & 3;
        uint32_t d = sbase + OFF_A + row * ASTRIDE + cq * 16;
        CP16(d, g_a + (size_t)(m0 + row) * JDIM + k0 + cq * 8);
    }
#pragma unroll
    for (int it = 0; it < 4; it++) {
        int c = tid + it * 256;            // 0..1023
        int row = c >> 2, cq = c & 3;
        uint32_t d = sbase + row * ASTRIDE + cq * 16;
        size_t gof = (size_t)(n0 + row) * JDIM + k0 + cq * 8;
        CP16(d + OFF_BHI, g_wt_hi + gof);
        CP16(d + OFF_BLO, g_wt_lo + gof);
    }
}

__global__ __launch_bounds__(256, 1) void joint_kernel(
    const float* __restrict__ bias, float* __restrict__ out)
{
    extern __shared__ char dsm[];
    const uint32_t sb = smem_u32(dsm);
    float* sbias = (float*)(dsm + 3 * STG_BYTES);

    const int tid = threadIdx.x;
    const int l   = tid & 31;
    const int w   = tid >> 5;
    const int mw  = w & 1;        // 0..1  -> 64-row slab
    const int nw  = w >> 1;       // 0..3  -> 64-col slab
    const int bid = blockIdx.x;
    const int n0  = (bid & 3) * BN;
    const int m0  = (bid >> 2) * BM;

    sbias[tid] = bias[n0 + tid];

    load_stage(sb + 0 * STG_BYTES, 0, m0, n0, tid);  CP_COMMIT();
    load_stage(sb + 1 * STG_BYTES, BK, m0, n0, tid); CP_COMMIT();

    float acc[4][8][4];
#pragma unroll
    for (int i = 0; i < 4; i++)
#pragma unroll
        for (int j = 0; j < 8; j++)
#pragma unroll
            for (int q = 0; q < 4; q++) acc[i][j][q] = 0.0f;

    const uint32_t a_off = (uint32_t)((mw * 64 + (l & 15)) * ASTRIDE + (l >> 4) * 16);
    const uint32_t b_off = (uint32_t)((nw * 64 + ((l >> 4) << 3) + (l & 7)) * ASTRIDE
                                      + ((l >> 3) & 1) * 16);

    for (int s = 0; s < NSTG; s++) {
        asm volatile("cp.async.wait_group 1;" ::: "memory");
        __syncthreads();
        if (s + 2 < NSTG)
            load_stage(sb + ((s + 2) % 3) * STG_BYTES, (s + 2) * BK, m0, n0, tid);
        CP_COMMIT();

        const uint32_t stg = sb + (s % 3) * STG_BYTES;
#pragma unroll
        for (int kk = 0; kk < 2; kk++) {
            const uint32_t ka = kk * 32;   // 16 fp16 = 32 bytes
            uint32_t aa[4][4], bb[4][4];
#pragma unroll
            for (int mf = 0; mf < 4; mf++)
                LDSM4(aa[mf], stg + OFF_A + a_off + ka + mf * 16 * ASTRIDE);
#pragma unroll
            for (int np = 0; np < 4; np++)
                LDSM4(bb[np], stg + OFF_BHI + b_off + ka + np * 16 * ASTRIDE);
            // pass 1: A * B_hi
#pragma unroll
            for (int mf = 0; mf < 4; mf++)
#pragma unroll
                for (int np = 0; np < 4; np++) {
                    MMA16816(acc[mf][np * 2 + 0], aa[mf], bb[np][0], bb[np][1]);
                    MMA16816(acc[mf][np * 2 + 1], aa[mf], bb[np][2], bb[np][3]);
                }
            // pass 2: A * B_lo (reuse bb regs)
#pragma unroll
            for (int np = 0; np < 4; np++)
                LDSM4(bb[np], stg + OFF_BLO + b_off + ka + np * 16 * ASTRIDE);
#pragma unroll
            for (int mf = 0; mf < 4; mf++)
#pragma unroll
                for (int np = 0; np < 4; np++) {
                    MMA16816(acc[mf][np * 2 + 0], aa[mf], bb[np][0], bb[np][1]);
                    MMA16816(acc[mf][np * 2 + 1], aa[mf], bb[np][2], bb[np][3]);
                }
        }
    }

    // epilogue: add bias, direct stores
#pragma unroll
    for (int mf = 0; mf < 4; mf++) {
        const int r0 = m0 + mw * 64 + mf * 16 + (l >> 2);
#pragma unroll
        for (int nf = 0; nf < 8; nf++) {
            const int c  = n0 + nw * 64 + nf * 8 + ((l & 3) << 1);
            const float2 b2 = *(const float2*)&sbias[c - n0];
            float2 o0, o1;
            o0.x = acc[mf][nf][0] + b2.x;
            o0.y = acc[mf][nf][1] + b2.y;
            o1.x = acc[mf][nf][2] + b2.x;
            o1.y = acc[mf][nf][3] + b2.y;
            *(float2*)&out[(size_t)r0 * VOCAB + c]       = o0;
            *(float2*)&out[(size_t)(r0 + 8) * VOCAB + c] = o1;
        }
    }
}

// ---------------------------------------------------------------------------
extern "C" void kernel_launch(void* const* d_in, const int* in_sizes, int n_in,
                              void* d_out, int out_size)
{
    const float* enc_out  = (const float*)d_in[0];
    const float* pred_out = (const float*)d_in[1];
    const float* W_enc    = (const float*)d_in[2];
    const float* b_enc    = (const float*)d_in[3];
    const float* W_pred   = (const float*)d_in[4];
    const float* b_pred   = (const float*)d_in[5];
    const float* W_joint  = (const float*)d_in[6];
    const float* b_joint  = (const float*)d_in[7];
    float* out = (float*)d_out;

    static bool attr_done = false;
    if (!attr_done) {
        cudaFuncSetAttribute(joint_kernel, cudaFuncAttributeMaxDynamicSharedMemorySize, JOINT_SMEM);
        attr_done = true;
    }

    {
        dim3 grid(JDIM / 128, (BB * TT) / 64);
        proj_kernel<ENC_DIM, 0><<<grid, 256>>>(enc_out, W_enc, b_enc);
    }
    {
        dim3 grid(JDIM / 128, (BB * UU) / 64);
        proj_kernel<PRED_DIM, 1><<<grid, 256>>>(pred_out, W_pred, b_pred);
    }
    prep_w_kernel<<<(VOCAB * JDIM) / 256, 256>>>(W_joint);
    prep_a_kernel<<<((size_t)MROWS * JDIM / 8) / 256, 256>>>();
    joint_kernel<<<(MROWS / BM) * (VOCAB / BN), 256, JOINT_SMEM>>>(b_joint, out);
}

// round 5
// speedup vs baseline: 2.3044x; 2.3044x over previous
#include <cuda_runtime.h>
#include <cuda_fp16.h>
#include <cstdint>

#define BB 8
#define TT 256
#define UU 64
#define ENC_DIM 512
#define PRED_DIM 640
#define JDIM 512
#define VOCAB 1024
#define MROWS (BB * TT * UU)   // 131072

// ---------------------------------------------------------------------------
// Device scratch
// ---------------------------------------------------------------------------
__device__ float g_enc_p[BB * TT * JDIM];            // 4 MB
__device__ float g_pred_p[BB * UU * JDIM];           // 1 MB
__device__ __half g_a[(size_t)MROWS * JDIM];         // 128 MB (fp16 tanh plane)
__device__ __half g_wt[VOCAB * JDIM];                // 1 MB  (W^T fp16)

// ---------------------------------------------------------------------------
// Helpers
// ---------------------------------------------------------------------------
__device__ __forceinline__ uint32_t smem_u32(const void* p) {
    uint32_t a;
    asm("{ .reg .u64 t; cvta.to.shared.u64 t, %1; cvt.u32.u64 %0, t; }" : "=r"(a) : "l"(p));
    return a;
}
#define CP16(dst, src) \
    asm volatile("cp.async.cg.shared.global [%0], [%1], 16;" :: "r"((uint32_t)(dst)), "l"(src) : "memory")
#define CP_COMMIT() asm volatile("cp.async.commit_group;" ::: "memory")

#define LDSM4(r, addr) \
    asm volatile("ldmatrix.sync.aligned.m8n8.x4.shared.b16 {%0,%1,%2,%3}, [%4];" \
                 : "=r"((r)[0]), "=r"((r)[1]), "=r"((r)[2]), "=r"((r)[3]) : "r"(addr))

#define MMA16816(acc, a, b0, b1) \
    asm volatile("mma.sync.aligned.m16n8k16.row.col.f32.f16.f16.f32 " \
                 "{%0,%1,%2,%3},{%4,%5,%6,%7},{%8,%9},{%0,%1,%2,%3};" \
                 : "+f"((acc)[0]), "+f"((acc)[1]), "+f"((acc)[2]), "+f"((acc)[3]) \
                 : "r"((a)[0]), "r"((a)[1]), "r"((a)[2]), "r"((a)[3]), "r"(b0), "r"(b1))

// HW tanh (MUFU.TANH, sm_75+): ~2^-11 accuracy, matches fp16 quantization scale
__device__ __forceinline__ float tanh_hw(float x) {
    float y;
    asm("tanh.approx.f32 %0, %1;" : "=f"(y) : "f"(x));
    return y;
}
__device__ __forceinline__ uint32_t pack2h(__half a, __half b) {
    return (uint32_t)__half_as_ushort(a) | ((uint32_t)__half_as_ushort(b) << 16);
}

// ---------------------------------------------------------------------------
// Projection GEMM (fp32 SIMT): C[M, 512] = A[M, K] @ W[K, 512] + bias
// ---------------------------------------------------------------------------
template <int K, int WHICH>
__global__ __launch_bounds__(256) void proj_kernel(
    const float* __restrict__ A, const float* __restrict__ W, const float* __restrict__ bias)
{
    __shared__ float As[16][68];
    __shared__ float Bs[16][128];
    float* __restrict__ C = (WHICH == 0) ? g_enc_p : g_pred_p;
    const int N = JDIM;
    const int tid = threadIdx.x;
    const int ty = tid >> 4, tx = tid & 15;
    const int m0 = blockIdx.y * 64, n0 = blockIdx.x * 128;
    const int lm = tid >> 2, lk = (tid & 3) << 2;

    float acc[4][8];
#pragma unroll
    for (int i = 0; i < 4; i++)
#pragma unroll
        for (int j = 0; j < 8; j++) acc[i][j] = 0.0f;

    for (int k0 = 0; k0 < K; k0 += 16) {
        float4 a4 = *(const float4*)&A[(m0 + lm) * K + k0 + lk];
        As[lk + 0][lm] = a4.x; As[lk + 1][lm] = a4.y;
        As[lk + 2][lm] = a4.z; As[lk + 3][lm] = a4.w;
#pragma unroll
        for (int r = 0; r < 2; r++) {
            int f = tid + r * 256;
            int kk = f >> 5, nn = (f & 31) << 2;
            *(float4*)&Bs[kk][nn] = *(const float4*)&W[(k0 + kk) * N + n0 + nn];
        }
        __syncthreads();
#pragma unroll
        for (int k = 0; k < 16; k++) {
            float4 av = *(const float4*)&As[k][ty << 2];
            float a[4] = {av.x, av.y, av.z, av.w};
            float bb[8];
#pragma unroll
            for (int j = 0; j < 8; j++) bb[j] = Bs[k][tx + (j << 4)];
#pragma unroll
            for (int i = 0; i < 4; i++)
#pragma unroll
                for (int j = 0; j < 8; j++) acc[i][j] = fmaf(a[i], bb[j], acc[i][j]);
        }
        __syncthreads();
    }
#pragma unroll
    for (int j = 0; j < 8; j++) {
        float bj = bias[n0 + tx + (j << 4)];
#pragma unroll
        for (int i = 0; i < 4; i++)
            C[(m0 + (ty << 2) + i) * N + n0 + tx + (j << 4)] = acc[i][j] + bj;
    }
}

// ---------------------------------------------------------------------------
// prep_W: Wt[v,k] = fp16(W_joint[k,v])
// ---------------------------------------------------------------------------
__global__ __launch_bounds__(256) void prep_w_kernel(const float* __restrict__ W) {
    int gid = blockIdx.x * 256 + threadIdx.x;       // 0 .. 524287
    int v = gid >> 9, k = gid & 511;
    g_wt[gid] = __float2half_rn(W[k * VOCAB + v]);
}

// ---------------------------------------------------------------------------
// prep_A: A[m,k] = fp16(tanh(enc_p[bt,k] + pred_p[b,u,k]))  (MUFU tanh)
// ---------------------------------------------------------------------------
__global__ __launch_bounds__(256) void prep_a_kernel() {
    int gid = blockIdx.x * 256 + threadIdx.x;       // 0 .. 8388607
    int m  = gid >> 6;
    int k8 = (gid & 63) << 3;
    int bt = m >> 6;
    int b  = bt >> 8;
    int u  = m & 63;
    const float4* e = (const float4*)(g_enc_p + (size_t)bt * JDIM + k8);
    const float4* p = (const float4*)(g_pred_p + ((size_t)(b * UU + u)) * JDIM + k8);

    __half h[8];
#pragma unroll
    for (int q = 0; q < 2; q++) {
        float4 ev = e[q], pv = p[q];
        h[q * 4 + 0] = __float2half_rn(tanh_hw(ev.x + pv.x));
        h[q * 4 + 1] = __float2half_rn(tanh_hw(ev.y + pv.y));
        h[q * 4 + 2] = __float2half_rn(tanh_hw(ev.z + pv.z));
        h[q * 4 + 3] = __float2half_rn(tanh_hw(ev.w + pv.w));
    }
    uint4 H;
    H.x = pack2h(h[0], h[1]); H.y = pack2h(h[2], h[3]);
    H.z = pack2h(h[4], h[5]); H.w = pack2h(h[6], h[7]);
    *(uint4*)(g_a + (size_t)m * JDIM + k8) = H;
}

// ---------------------------------------------------------------------------
// Joint GEMM via mma.sync (HMMA): C = A_fp16 @ Wt_fp16^T + bias  (single pass)
// BM=128, BN=256, BK=32, 256 threads (8 warps 2x4), warp tile 64x64.
// 3-stage cp.async pipeline.
// ---------------------------------------------------------------------------
#define BM 128
#define BN 256
#define BK 32
#define NSTG 16                         // 512 / 32
#define ASTRIDE 80                      // 32 fp16 = 64B data, padded to 80B
#define A_PLANE (BM * ASTRIDE)          // 10240
#define B_PLANE (BN * ASTRIDE)          // 20480
#define STG_BYTES (A_PLANE + B_PLANE)   // 30720
#define OFF_A 0
#define OFF_B A_PLANE
#define JOINT_SMEM (3 * STG_BYTES + 1024)      // + bias

__device__ __forceinline__ void load_stage(uint32_t sbase, int k0, int m0, int n0, int tid) {
#pragma unroll
    for (int it = 0; it < 2; it++) {
        int c = tid + it * 256;            // 0..511
        int row = c >> 2, cq = c & 3;
        CP16(sbase + OFF_A + row * ASTRIDE + cq * 16,
             g_a + (size_t)(m0 + row) * JDIM + k0 + cq * 8);
    }
#pragma unroll
    for (int it = 0; it < 4; it++) {
        int c = tid + it * 256;            // 0..1023
        int row = c >> 2, cq = c & 3;
        CP16(sbase + OFF_B + row * ASTRIDE + cq * 16,
             g_wt + (size_t)(n0 + row) * JDIM + k0 + cq * 8);
    }
}

__global__ __launch_bounds__(256, 1) void joint_kernel(
    const float* __restrict__ bias, float* __restrict__ out)
{
    extern __shared__ char dsm[];
    const uint32_t sb = smem_u32(dsm);
    float* sbias = (float*)(dsm + 3 * STG_BYTES);

    const int tid = threadIdx.x;
    const int l   = tid & 31;
    const int w   = tid >> 5;
    const int mw  = w & 1;        // 0..1  -> 64-row slab
    const int nw  = w >> 1;       // 0..3  -> 64-col slab
    const int bid = blockIdx.x;
    const int n0  = (bid & 3) * BN;
    const int m0  = (bid >> 2) * BM;

    sbias[tid] = bias[n0 + tid];

    load_stage(sb + 0 * STG_BYTES, 0, m0, n0, tid);  CP_COMMIT();
    load_stage(sb + 1 * STG_BYTES, BK, m0, n0, tid); CP_COMMIT();

    float acc[4][8][4];
#pragma unroll
    for (int i = 0; i < 4; i++)
#pragma unroll
        for (int j = 0; j < 8; j++)
#pragma unroll
            for (int q = 0; q < 4; q++) acc[i][j][q] = 0.0f;

    const uint32_t a_off = (uint32_t)((mw * 64 + (l & 15)) * ASTRIDE + (l >> 4) * 16);
    const uint32_t b_off = (uint32_t)((nw * 64 + ((l >> 4) << 3) + (l & 7)) * ASTRIDE
                                      + ((l >> 3) & 1) * 16);

    for (int s = 0; s < NSTG; s++) {
        asm volatile("cp.async.wait_group 1;" ::: "memory");
        __syncthreads();
        if (s + 2 < NSTG)
            load_stage(sb + ((s + 2) % 3) * STG_BYTES, (s + 2) * BK, m0, n0, tid);
        CP_COMMIT();

        const uint32_t stg = sb + (s % 3) * STG_BYTES;
#pragma unroll
        for (int kk = 0; kk < 2; kk++) {
            const uint32_t ka = kk * 32;   // 16 fp16 = 32 bytes
            uint32_t aa[4][4], bb[4][4];
#pragma unroll
            for (int mf = 0; mf < 4; mf++)
                LDSM4(aa[mf], stg + OFF_A + a_off + ka + mf * 16 * ASTRIDE);
#pragma unroll
            for (int np = 0; np < 4; np++)
                LDSM4(bb[np], stg + OFF_B + b_off + ka + np * 16 * ASTRIDE);
#pragma unroll
            for (int mf = 0; mf < 4; mf++)
#pragma unroll
                for (int np = 0; np < 4; np++) {
                    MMA16816(acc[mf][np * 2 + 0], aa[mf], bb[np][0], bb[np][1]);
                    MMA16816(acc[mf][np * 2 + 1], aa[mf], bb[np][2], bb[np][3]);
                }
        }
    }

    // epilogue: add bias, direct stores
#pragma unroll
    for (int mf = 0; mf < 4; mf++) {
        const int r0 = m0 + mw * 64 + mf * 16 + (l >> 2);
#pragma unroll
        for (int nf = 0; nf < 8; nf++) {
            const int c  = n0 + nw * 64 + nf * 8 + ((l & 3) << 1);
            const float2 b2 = *(const float2*)&sbias[c - n0];
            float2 o0, o1;
            o0.x = acc[mf][nf][0] + b2.x;
            o0.y = acc[mf][nf][1] + b2.y;
            o1.x = acc[mf][nf][2] + b2.x;
            o1.y = acc[mf][nf][3] + b2.y;
            *(float2*)&out[(size_t)r0 * VOCAB + c]       = o0;
            *(float2*)&out[(size_t)(r0 + 8) * VOCAB + c] = o1;
        }
    }
}

// ---------------------------------------------------------------------------
extern "C" void kernel_launch(void* const* d_in, const int* in_sizes, int n_in,
                              void* d_out, int out_size)
{
    const float* enc_out  = (const float*)d_in[0];
    const float* pred_out = (const float*)d_in[1];
    const float* W_enc    = (const float*)d_in[2];
    const float* b_enc    = (const float*)d_in[3];
    const float* W_pred   = (const float*)d_in[4];
    const float* b_pred   = (const float*)d_in[5];
    const float* W_joint  = (const float*)d_in[6];
    const float* b_joint  = (const float*)d_in[7];
    float* out = (float*)d_out;

    static bool attr_done = false;
    if (!attr_done) {
        cudaFuncSetAttribute(joint_kernel, cudaFuncAttributeMaxDynamicSharedMemorySize, JOINT_SMEM);
        attr_done = true;
    }

    {
        dim3 grid(JDIM / 128, (BB * TT) / 64);
        proj_kernel<ENC_DIM, 0><<<grid, 256>>>(enc_out, W_enc, b_enc);
    }
    {
        dim3 grid(JDIM / 128, (BB * UU) / 64);
        proj_kernel<PRED_DIM, 1><<<grid, 256>>>(pred_out, W_pred, b_pred);
    }
    prep_w_kernel<<<(VOCAB * JDIM) / 256, 256>>>(W_joint);
    prep_a_kernel<<<((size_t)MROWS * JDIM / 8) / 256, 256>>>();
    joint_kernel<<<(MROWS / BM) * (VOCAB / BN), 256, JOINT_SMEM>>>(b_joint, out);
}

// round 7
// speedup vs baseline: 2.5344x; 1.0998x over previous
#include <cuda_runtime.h>
#include <cuda_fp16.h>
#include <cstdint>

#define BB 8
#define TT 256
#define UU 64
#define ENC_DIM 512
#define PRED_DIM 640
#define JDIM 512
#define VOCAB 1024
#define MROWS (BB * TT * UU)   // 131072

// ---------------------------------------------------------------------------
// Device scratch
// ---------------------------------------------------------------------------
__device__ float g_enc_p[BB * TT * JDIM];            // 4 MB
__device__ float g_pred_p[BB * UU * JDIM];           // 1 MB
__device__ __half g_a[(size_t)MROWS * JDIM];         // 128 MB (fp16 tanh plane)
__device__ __half g_wt[VOCAB * JDIM];                // 1 MB  (W^T fp16)

// ---------------------------------------------------------------------------
// Helpers
// ---------------------------------------------------------------------------
__device__ __forceinline__ uint32_t smem_u32(const void* p) {
    uint32_t a;
    asm("{ .reg .u64 t; cvta.to.shared.u64 t, %1; cvt.u32.u64 %0, t; }" : "=r"(a) : "l"(p));
    return a;
}
#define CP16(dst, src) \
    asm volatile("cp.async.cg.shared.global [%0], [%1], 16;" :: "r"((uint32_t)(dst)), "l"(src) : "memory")
#define CP_COMMIT() asm volatile("cp.async.commit_group;" ::: "memory")

#define LDSM4(r, addr) \
    asm volatile("ldmatrix.sync.aligned.m8n8.x4.shared.b16 {%0,%1,%2,%3}, [%4];" \
                 : "=r"((r)[0]), "=r"((r)[1]), "=r"((r)[2]), "=r"((r)[3]) : "r"(addr))

#define MMA16816(acc, a, b0, b1) \
    asm volatile("mma.sync.aligned.m16n8k16.row.col.f32.f16.f16.f32 " \
                 "{%0,%1,%2,%3},{%4,%5,%6,%7},{%8,%9},{%0,%1,%2,%3};" \
                 : "+f"((acc)[0]), "+f"((acc)[1]), "+f"((acc)[2]), "+f"((acc)[3]) \
                 : "r"((a)[0]), "r"((a)[1]), "r"((a)[2]), "r"((a)[3]), "r"(b0), "r"(b1))

// HW tanh (MUFU.TANH): ~2^-11 accuracy, matches fp16 quantization scale
__device__ __forceinline__ float tanh_hw(float x) {
    float y;
    asm("tanh.approx.f32 %0, %1;" : "=f"(y) : "f"(x));
    return y;
}
__device__ __forceinline__ uint32_t pack2h(__half a, __half b) {
    return (uint32_t)__half_as_ushort(a) | ((uint32_t)__half_as_ushort(b) << 16);
}

// ---------------------------------------------------------------------------
// Projection GEMM (fp32 SIMT): C[M, 512] = A[M, K] @ W[K, 512] + bias
// ---------------------------------------------------------------------------
template <int K, int WHICH>
__global__ __launch_bounds__(256) void proj_kernel(
    const float* __restrict__ A, const float* __restrict__ W, const float* __restrict__ bias)
{
    __shared__ float As[16][68];
    __shared__ float Bs[16][128];
    float* __restrict__ C = (WHICH == 0) ? g_enc_p : g_pred_p;
    const int N = JDIM;
    const int tid = threadIdx.x;
    const int ty = tid >> 4, tx = tid & 15;
    const int m0 = blockIdx.y * 64, n0 = blockIdx.x * 128;
    const int lm = tid >> 2, lk = (tid & 3) << 2;

    float acc[4][8];
#pragma unroll
    for (int i = 0; i < 4; i++)
#pragma unroll
        for (int j = 0; j < 8; j++) acc[i][j] = 0.0f;

    for (int k0 = 0; k0 < K; k0 += 16) {
        float4 a4 = *(const float4*)&A[(m0 + lm) * K + k0 + lk];
        As[lk + 0][lm] = a4.x; As[lk + 1][lm] = a4.y;
        As[lk + 2][lm] = a4.z; As[lk + 3][lm] = a4.w;
#pragma unroll
        for (int r = 0; r < 2; r++) {
            int f = tid + r * 256;
            int kk = f >> 5, nn = (f & 31) << 2;
            *(float4*)&Bs[kk][nn] = *(const float4*)&W[(k0 + kk) * N + n0 + nn];
        }
        __syncthreads();
#pragma unroll
        for (int k = 0; k < 16; k++) {
            float4 av = *(const float4*)&As[k][ty << 2];
            float a[4] = {av.x, av.y, av.z, av.w};
            float bb[8];
#pragma unroll
            for (int j = 0; j < 8; j++) bb[j] = Bs[k][tx + (j << 4)];
#pragma unroll
            for (int i = 0; i < 4; i++)
#pragma unroll
                for (int j = 0; j < 8; j++) acc[i][j] = fmaf(a[i], bb[j], acc[i][j]);
        }
        __syncthreads();
    }
#pragma unroll
    for (int j = 0; j < 8; j++) {
        float bj = bias[n0 + tx + (j << 4)];
#pragma unroll
        for (int i = 0; i < 4; i++)
            C[(m0 + (ty << 2) + i) * N + n0 + tx + (j << 4)] = acc[i][j] + bj;
    }
}

// ---------------------------------------------------------------------------
// prep_W: Wt[v,k] = fp16(W_joint[k,v])
// ---------------------------------------------------------------------------
__global__ __launch_bounds__(256) void prep_w_kernel(const float* __restrict__ W) {
    int gid = blockIdx.x * 256 + threadIdx.x;       // 0 .. 524287
    int v = gid >> 9, k = gid & 511;
    g_wt[gid] = __float2half_rn(W[k * VOCAB + v]);
}

// ---------------------------------------------------------------------------
// prep_A: A[m,k] = fp16(tanh(enc_p[bt,k] + pred_p[b,u,k]))  (MUFU tanh)
// ---------------------------------------------------------------------------
__global__ __launch_bounds__(256) void prep_a_kernel() {
    int gid = blockIdx.x * 256 + threadIdx.x;       // 0 .. 8388607
    int m  = gid >> 6;
    int k8 = (gid & 63) << 3;
    int bt = m >> 6;
    int b  = bt >> 8;
    int u  = m & 63;
    const float4* e = (const float4*)(g_enc_p + (size_t)bt * JDIM + k8);
    const float4* p = (const float4*)(g_pred_p + ((size_t)(b * UU + u)) * JDIM + k8);

    __half h[8];
#pragma unroll
    for (int q = 0; q < 2; q++) {
        float4 ev = e[q], pv = p[q];
        h[q * 4 + 0] = __float2half_rn(tanh_hw(ev.x + pv.x));
        h[q * 4 + 1] = __float2half_rn(tanh_hw(ev.y + pv.y));
        h[q * 4 + 2] = __float2half_rn(tanh_hw(ev.z + pv.z));
        h[q * 4 + 3] = __float2half_rn(tanh_hw(ev.w + pv.w));
    }
    uint4 H;
    H.x = pack2h(h[0], h[1]); H.y = pack2h(h[2], h[3]);
    H.z = pack2h(h[4], h[5]); H.w = pack2h(h[6], h[7]);
    *(uint4*)(g_a + (size_t)m * JDIM + k8) = H;
}

// ---------------------------------------------------------------------------
// Joint GEMM via mma.sync (HMMA): C = A_fp16 @ Wt_fp16^T + bias  (single pass)
// BM=128, BN=256, BK=32, 256 threads (8 warps 2x4), warp tile 64x64.
// 4-stage cp.async pipeline; all LDSM for a stage hoisted ahead of the MMA
// block so fragment loads decouple from tensor-pipe drain.
// ---------------------------------------------------------------------------
#define BM 128
#define BN 256
#define BK 32
#define NSTG 16                         // 512 / 32
#define NPIPE 4
#define ASTRIDE 80                      // 32 fp16 = 64B data, padded to 80B
#define A_PLANE (BM * ASTRIDE)          // 10240
#define B_PLANE (BN * ASTRIDE)          // 20480
#define STG_BYTES (A_PLANE + B_PLANE)   // 30720
#define OFF_A 0
#define OFF_B A_PLANE
#define JOINT_SMEM (NPIPE * STG_BYTES + 1024)  // + bias

__device__ __forceinline__ void load_stage(uint32_t sbase, int k0, int m0, int n0, int tid) {
#pragma unroll
    for (int it = 0; it < 2; it++) {
        int c = tid + it * 256;            // 0..511
        int row = c >> 2, cq = c & 3;
        CP16(sbase + OFF_A + row * ASTRIDE + cq * 16,
             g_a + (size_t)(m0 + row) * JDIM + k0 + cq * 8);
    }
#pragma unroll
    for (int it = 0; it < 4; it++) {
        int c = tid + it * 256;            // 0..1023
        int row = c >> 2, cq = c & 3;
        CP16(sbase + OFF_B + row * ASTRIDE + cq * 16,
             g_wt + (size_t)(n0 + row) * JDIM + k0 + cq * 8);
    }
}

__global__ __launch_bounds__(256, 1) void joint_kernel(
    const float* __restrict__ bias, float* __restrict__ out)
{
    extern __shared__ char dsm[];
    const uint32_t sb = smem_u32(dsm);
    float* sbias = (float*)(dsm + NPIPE * STG_BYTES);

    const int tid = threadIdx.x;
    const int l   = tid & 31;
    const int w   = tid >> 5;
    const int mw  = w & 1;        // 0..1  -> 64-row slab
    const int nw  = w >> 1;       // 0..3  -> 64-col slab
    const int bid = blockIdx.x;
    const int n0  = (bid & 3) * BN;
    const int m0  = (bid >> 2) * BM;

    sbias[tid] = bias[n0 + tid];

    load_stage(sb + 0 * STG_BYTES, 0 * BK, m0, n0, tid); CP_COMMIT();
    load_stage(sb + 1 * STG_BYTES, 1 * BK, m0, n0, tid); CP_COMMIT();
    load_stage(sb + 2 * STG_BYTES, 2 * BK, m0, n0, tid); CP_COMMIT();

    float acc[4][8][4];
#pragma unroll
    for (int i = 0; i < 4; i++)
#pragma unroll
        for (int j = 0; j < 8; j++)
#pragma unroll
            for (int q = 0; q < 4; q++) acc[i][j][q] = 0.0f;

    const uint32_t a_off = (uint32_t)((mw * 64 + (l & 15)) * ASTRIDE + (l >> 4) * 16);
    const uint32_t b_off = (uint32_t)((nw * 64 + ((l >> 4) << 3) + (l & 7)) * ASTRIDE
                                      + ((l >> 3) & 1) * 16);

    // stage 0 resident
    asm volatile("cp.async.wait_group 2;" ::: "memory");
    __syncthreads();

    for (int s = 0; s < NSTG; s++) {
        const uint32_t stg = sb + (s & (NPIPE - 1)) * STG_BYTES;

        // 1) all fragment loads for this stage (both k-halves)
        uint32_t aa[2][4][4], bb[2][4][4];
#pragma unroll
        for (int kk = 0; kk < 2; kk++) {
#pragma unroll
            for (int mf = 0; mf < 4; mf++)
                LDSM4(aa[kk][mf], stg + OFF_A + a_off + kk * 32 + mf * 16 * ASTRIDE);
#pragma unroll
            for (int np = 0; np < 4; np++)
                LDSM4(bb[kk][np], stg + OFF_B + b_off + kk * 32 + np * 16 * ASTRIDE);
        }

        // 2) prefetch stage s+3 in the LDSM shadow (uniform commit keeps
        //    outstanding-group count constant)
        if (s + 3 < NSTG)
            load_stage(sb + ((s + 3) & (NPIPE - 1)) * STG_BYTES, (s + 3) * BK, m0, n0, tid);
        CP_COMMIT();

        // 3) MMAs (register-only dependencies)
#pragma unroll
        for (int kk = 0; kk < 2; kk++)
#pragma unroll
            for (int mf = 0; mf < 4; mf++)
#pragma unroll
                for (int np = 0; np < 4; np++) {
                    MMA16816(acc[mf][np * 2 + 0], aa[kk][mf], bb[kk][np][0], bb[kk][np][1]);
                    MMA16816(acc[mf][np * 2 + 1], aa[kk][mf], bb[kk][np][2], bb[kk][np][3]);
                }

        // 4) arrival of stage s+1 overlaps MMA drain
        asm volatile("cp.async.wait_group 2;" ::: "memory");
        __syncthreads();
    }

    // epilogue: add bias, direct stores
#pragma unroll
    for (int mf = 0; mf < 4; mf++) {
        const int r0 = m0 + mw * 64 + mf * 16 + (l >> 2);
#pragma unroll
        for (int nf = 0; nf < 8; nf++) {
            const int c  = n0 + nw * 64 + nf * 8 + ((l & 3) << 1);
            const float2 b2 = *(const float2*)&sbias[c - n0];
            float2 o0, o1;
            o0.x = acc[mf][nf][0] + b2.x;
            o0.y = acc[mf][nf][1] + b2.y;
            o1.x = acc[mf][nf][2] + b2.x;
            o1.y = acc[mf][nf][3] + b2.y;
            *(float2*)&out[(size_t)r0 * VOCAB + c]       = o0;
            *(float2*)&out[(size_t)(r0 + 8) * VOCAB + c] = o1;
        }
    }
}

// ---------------------------------------------------------------------------
extern "C" void kernel_launch(void* const* d_in, const int* in_sizes, int n_in,
                              void* d_out, int out_size)
{
    const float* enc_out  = (const float*)d_in[0];
    const float* pred_out = (const float*)d_in[1];
    const float* W_enc    = (const float*)d_in[2];
    const float* b_enc    = (const float*)d_in[3];
    const float* W_pred   = (const float*)d_in[4];
    const float* b_pred   = (const float*)d_in[5];
    const float* W_joint  = (const float*)d_in[6];
    const float* b_joint  = (const float*)d_in[7];
    float* out = (float*)d_out;

    static bool attr_done = false;
    if (!attr_done) {
        cudaFuncSetAttribute(joint_kernel, cudaFuncAttributeMaxDynamicSharedMemorySize, JOINT_SMEM);
        attr_done = true;
    }

    {
        dim3 grid(JDIM / 128, (BB * TT) / 64);
        proj_kernel<ENC_DIM, 0><<<grid, 256>>>(enc_out, W_enc, b_enc);
    }
    {
        dim3 grid(JDIM / 128, (BB * UU) / 64);
        proj_kernel<PRED_DIM, 1><<<grid, 256>>>(pred_out, W_pred, b_pred);
    }
    prep_w_kernel<<<(VOCAB * JDIM) / 256, 256>>>(W_joint);
    prep_a_kernel<<<((size_t)MROWS * JDIM / 8) / 256, 256>>>();
    joint_kernel<<<(MROWS / BM) * (VOCAB / BN), 256, JOINT_SMEM>>>(b_joint, out);
}

// round 8
// speedup vs baseline: 2.7495x; 1.0849x over previous
#include <cuda_runtime.h>
#include <cuda_fp16.h>
#include <cstdint>

#define BB 8
#define TT 256
#define UU 64
#define ENC_DIM 512
#define PRED_DIM 640
#define JDIM 512
#define VOCAB 1024
#define MROWS (BB * TT * UU)   // 131072

// ---------------------------------------------------------------------------
// Device scratch
// ---------------------------------------------------------------------------
__device__ float g_enc_p[BB * TT * JDIM];            // 4 MB
__device__ float g_pred_p[BB * UU * JDIM];           // 1 MB
__device__ __half g_a[(size_t)MROWS * JDIM];         // 128 MB (fp16 tanh plane)
__device__ __half g_wt[VOCAB * JDIM];                // 1 MB  (W^T fp16)

// ---------------------------------------------------------------------------
// Helpers
// ---------------------------------------------------------------------------
__device__ __forceinline__ uint32_t smem_u32(const void* p) {
    uint32_t a;
    asm("{ .reg .u64 t; cvta.to.shared.u64 t, %1; cvt.u32.u64 %0, t; }" : "=r"(a) : "l"(p));
    return a;
}
#define CP16(dst, src) \
    asm volatile("cp.async.cg.shared.global [%0], [%1], 16;" :: "r"((uint32_t)(dst)), "l"(src) : "memory")
#define CP_COMMIT() asm volatile("cp.async.commit_group;" ::: "memory")

#define LDSM4(r, addr) \
    asm volatile("ldmatrix.sync.aligned.m8n8.x4.shared.b16 {%0,%1,%2,%3}, [%4];" \
                 : "=r"((r)[0]), "=r"((r)[1]), "=r"((r)[2]), "=r"((r)[3]) : "r"(addr))

#define MMA16816(acc, a, b0, b1) \
    asm volatile("mma.sync.aligned.m16n8k16.row.col.f32.f16.f16.f32 " \
                 "{%0,%1,%2,%3},{%4,%5,%6,%7},{%8,%9},{%0,%1,%2,%3};" \
                 : "+f"((acc)[0]), "+f"((acc)[1]), "+f"((acc)[2]), "+f"((acc)[3]) \
                 : "r"((a)[0]), "r"((a)[1]), "r"((a)[2]), "r"((a)[3]), "r"(b0), "r"(b1))

// HW tanh (MUFU.TANH): ~2^-11 accuracy, matches fp16 quantization scale
__device__ __forceinline__ float tanh_hw(float x) {
    float y;
    asm("tanh.approx.f32 %0, %1;" : "=f"(y) : "f"(x));
    return y;
}
__device__ __forceinline__ uint32_t pack2h(__half a, __half b) {
    return (uint32_t)__half_as_ushort(a) | ((uint32_t)__half_as_ushort(b) << 16);
}

// ---------------------------------------------------------------------------
// Projection GEMM (fp32 SIMT): C[M, 512] = A[M, K] @ W[K, 512] + bias
// BM=64, BN=64, 256 threads, 4x4 microtile -> 256 blocks for enc (better occ)
// ---------------------------------------------------------------------------
template <int K, int WHICH>
__global__ __launch_bounds__(256) void proj_kernel(
    const float* __restrict__ A, const float* __restrict__ W, const float* __restrict__ bias)
{
    __shared__ float As[16][68];
    __shared__ float Bs[16][68];
    float* __restrict__ C = (WHICH == 0) ? g_enc_p : g_pred_p;
    const int N = JDIM;
    const int tid = threadIdx.x;
    const int ty = tid >> 4, tx = tid & 15;       // 16 x 16 thread grid
    const int m0 = blockIdx.y * 64, n0 = blockIdx.x * 64;
    const int lm = tid >> 2, lk = (tid & 3) << 2; // A loader
    const int bk = tid >> 4, bn = (tid & 15) << 2; // B loader

    float acc[4][4];
#pragma unroll
    for (int i = 0; i < 4; i++)
#pragma unroll
        for (int j = 0; j < 4; j++) acc[i][j] = 0.0f;

    for (int k0 = 0; k0 < K; k0 += 16) {
        float4 a4 = *(const float4*)&A[(m0 + lm) * K + k0 + lk];
        As[lk + 0][lm] = a4.x; As[lk + 1][lm] = a4.y;
        As[lk + 2][lm] = a4.z; As[lk + 3][lm] = a4.w;
        *(float4*)&Bs[bk][bn] = *(const float4*)&W[(k0 + bk) * N + n0 + bn];
        __syncthreads();
#pragma unroll
        for (int k = 0; k < 16; k++) {
            float4 av = *(const float4*)&As[k][ty << 2];
            float4 bv = *(const float4*)&Bs[k][tx << 2];
            float a[4] = {av.x, av.y, av.z, av.w};
            float b[4] = {bv.x, bv.y, bv.z, bv.w};
#pragma unroll
            for (int i = 0; i < 4; i++)
#pragma unroll
                for (int j = 0; j < 4; j++) acc[i][j] = fmaf(a[i], b[j], acc[i][j]);
        }
        __syncthreads();
    }
#pragma unroll
    for (int j = 0; j < 4; j++) {
        float bj = bias[n0 + (tx << 2) + j];
#pragma unroll
        for (int i = 0; i < 4; i++)
            C[(m0 + (ty << 2) + i) * N + n0 + (tx << 2) + j] = acc[i][j] + bj;
    }
}

// ---------------------------------------------------------------------------
// prep_W: Wt[v,k] = fp16(W_joint[k,v])
// ---------------------------------------------------------------------------
__global__ __launch_bounds__(256) void prep_w_kernel(const float* __restrict__ W) {
    int gid = blockIdx.x * 256 + threadIdx.x;       // 0 .. 524287
    int v = gid >> 9, k = gid & 511;
    g_wt[gid] = __float2half_rn(W[k * VOCAB + v]);
}

// ---------------------------------------------------------------------------
// prep_A: A[m,k] = fp16(tanh(enc_p[bt,k] + pred_p[b,u,k]))  (MUFU tanh)
// Each thread handles (bt, k8) for u and u+32 -> enc row load shared, MLP=6.
// ---------------------------------------------------------------------------
__global__ __launch_bounds__(256) void prep_a_kernel() {
    int gid = blockIdx.x * 256 + threadIdx.x;       // 0 .. 4194303
    int bt = gid >> 11;                 // 2048 threads per bt
    int r  = gid & 2047;
    int u  = r >> 6;                    // 0..31
    int k8 = (r & 63) << 3;
    int b  = bt >> 8;

    const float4* e  = (const float4*)(g_enc_p + (size_t)bt * JDIM + k8);
    const float4* p0 = (const float4*)(g_pred_p + ((size_t)(b * UU + u)) * JDIM + k8);
    const float4* p1 = (const float4*)(g_pred_p + ((size_t)(b * UU + u + 32)) * JDIM + k8);

    float4 e0 = e[0],  e1 = e[1];
    float4 pa = p0[0], pb = p0[1];
    float4 pc = p1[0], pd = p1[1];

    __half h0[8], h1[8];
    h0[0] = __float2half_rn(tanh_hw(e0.x + pa.x));
    h0[1] = __float2half_rn(tanh_hw(e0.y + pa.y));
    h0[2] = __float2half_rn(tanh_hw(e0.z + pa.z));
    h0[3] = __float2half_rn(tanh_hw(e0.w + pa.w));
    h0[4] = __float2half_rn(tanh_hw(e1.x + pb.x));
    h0[5] = __float2half_rn(tanh_hw(e1.y + pb.y));
    h0[6] = __float2half_rn(tanh_hw(e1.z + pb.z));
    h0[7] = __float2half_rn(tanh_hw(e1.w + pb.w));
    h1[0] = __float2half_rn(tanh_hw(e0.x + pc.x));
    h1[1] = __float2half_rn(tanh_hw(e0.y + pc.y));
    h1[2] = __float2half_rn(tanh_hw(e0.z + pc.z));
    h1[3] = __float2half_rn(tanh_hw(e0.w + pc.w));
    h1[4] = __float2half_rn(tanh_hw(e1.x + pd.x));
    h1[5] = __float2half_rn(tanh_hw(e1.y + pd.y));
    h1[6] = __float2half_rn(tanh_hw(e1.z + pd.z));
    h1[7] = __float2half_rn(tanh_hw(e1.w + pd.w));

    uint4 H0, H1;
    H0.x = pack2h(h0[0], h0[1]); H0.y = pack2h(h0[2], h0[3]);
    H0.z = pack2h(h0[4], h0[5]); H0.w = pack2h(h0[6], h0[7]);
    H1.x = pack2h(h1[0], h1[1]); H1.y = pack2h(h1[2], h1[3]);
    H1.z = pack2h(h1[4], h1[5]); H1.w = pack2h(h1[6], h1[7]);
    size_t m0 = (size_t)(bt * UU + u) * JDIM + k8;
    *(uint4*)(g_a + m0)                      = H0;
    *(uint4*)(g_a + m0 + (size_t)32 * JDIM)  = H1;
}

// ---------------------------------------------------------------------------
// Joint GEMM via mma.sync (HMMA): C = A_fp16 @ Wt_fp16^T + bias  (single pass)
// BM=128, BN=256, BK=64, 256 threads (8 warps 2x4), warp tile 64x64.
// 8 stages, NPIPE=3 cp.async pipeline; LDSM hoisted per kk-pair; half the
// barrier/wait overhead of the BK=32 version.
// ---------------------------------------------------------------------------
#define BM 128
#define BN 256
#define BK 64
#define NSTG 8                          // 512 / 64
#define NPIPE 3
#define ASTRIDE 144                     // 64 fp16 = 128B data, padded to 144B
#define A_PLANE (BM * ASTRIDE)          // 18432
#define B_PLANE (BN * ASTRIDE)          // 36864
#define STG_BYTES (A_PLANE + B_PLANE)   // 55296
#define OFF_A 0
#define OFF_B A_PLANE
#define JOINT_SMEM (NPIPE * STG_BYTES + 1024)  // 166912 (+bias)

__device__ __forceinline__ void load_stage(uint32_t sbase, int k0, int m0, int n0, int tid) {
#pragma unroll
    for (int it = 0; it < 4; it++) {
        int c = tid + it * 256;            // 0..1023
        int row = c >> 3, cq = c & 7;
        CP16(sbase + OFF_A + row * ASTRIDE + cq * 16,
             g_a + (size_t)(m0 + row) * JDIM + k0 + cq * 8);
    }
#pragma unroll
    for (int it = 0; it < 8; it++) {
        int c = tid + it * 256;            // 0..2047
        int row = c >> 3, cq = c & 7;
        CP16(sbase + OFF_B + row * ASTRIDE + cq * 16,
             g_wt + (size_t)(n0 + row) * JDIM + k0 + cq * 8);
    }
}

__global__ __launch_bounds__(256, 1) void joint_kernel(
    const float* __restrict__ bias, float* __restrict__ out)
{
    extern __shared__ char dsm[];
    const uint32_t sb = smem_u32(dsm);
    float* sbias = (float*)(dsm + NPIPE * STG_BYTES);

    const int tid = threadIdx.x;
    const int l   = tid & 31;
    const int w   = tid >> 5;
    const int mw  = w & 1;        // 0..1  -> 64-row slab
    const int nw  = w >> 1;       // 0..3  -> 64-col slab
    const int bid = blockIdx.x;
    const int n0  = (bid & 3) * BN;
    const int m0  = (bid >> 2) * BM;

    sbias[tid] = bias[n0 + tid];

    load_stage(sb + 0 * STG_BYTES, 0 * BK, m0, n0, tid); CP_COMMIT();
    load_stage(sb + 1 * STG_BYTES, 1 * BK, m0, n0, tid); CP_COMMIT();

    float acc[4][8][4];
#pragma unroll
    for (int i = 0; i < 4; i++)
#pragma unroll
        for (int j = 0; j < 8; j++)
#pragma unroll
            for (int q = 0; q < 4; q++) acc[i][j][q] = 0.0f;

    const uint32_t a_off = (uint32_t)((mw * 64 + (l & 15)) * ASTRIDE + (l >> 4) * 16);
    const uint32_t b_off = (uint32_t)((nw * 64 + ((l >> 4) << 3) + (l & 7)) * ASTRIDE
                                      + ((l >> 3) & 1) * 16);

    for (int s = 0; s < NSTG; s++) {
        // stage s resident (2 groups may be in flight; keep 1)
        asm volatile("cp.async.wait_group 1;" ::: "memory");
        __syncthreads();

        const uint32_t stg = sb + (s % NPIPE) * STG_BYTES;
        uint32_t aa[2][4][4], bb[2][4][4];

        // ---- kk-pair 0 (kk = 0,1) ----
#pragma unroll
        for (int kk = 0; kk < 2; kk++) {
#pragma unroll
            for (int mf = 0; mf < 4; mf++)
                LDSM4(aa[kk][mf], stg + OFF_A + a_off + kk * 32 + mf * 16 * ASTRIDE);
#pragma unroll
            for (int np = 0; np < 4; np++)
                LDSM4(bb[kk][np], stg + OFF_B + b_off + kk * 32 + np * 16 * ASTRIDE);
        }
        // prefetch stage s+2 in the LDSM/MMA shadow (uniform commit)
        if (s + 2 < NSTG)
            load_stage(sb + ((s + 2) % NPIPE) * STG_BYTES, (s + 2) * BK, m0, n0, tid);
        CP_COMMIT();
#pragma unroll
        for (int kk = 0; kk < 2; kk++)
#pragma unroll
            for (int mf = 0; mf < 4; mf++)
#pragma unroll
                for (int np = 0; np < 4; np++) {
                    MMA16816(acc[mf][np * 2 + 0], aa[kk][mf], bb[kk][np][0], bb[kk][np][1]);
                    MMA16816(acc[mf][np * 2 + 1], aa[kk][mf], bb[kk][np][2], bb[kk][np][3]);
                }

        // ---- kk-pair 1 (kk = 2,3), registers reused ----
#pragma unroll
        for (int kk = 0; kk < 2; kk++) {
#pragma unroll
            for (int mf = 0; mf < 4; mf++)
                LDSM4(aa[kk][mf], stg + OFF_A + a_off + 64 + kk * 32 + mf * 16 * ASTRIDE);
#pragma unroll
            for (int np = 0; np < 4; np++)
                LDSM4(bb[kk][np], stg + OFF_B + b_off + 64 + kk * 32 + np * 16 * ASTRIDE);
        }
#pragma unroll
        for (int kk = 0; kk < 2; kk++)
#pragma unroll
            for (int mf = 0; mf < 4; mf++)
#pragma unroll
                for (int np = 0; np < 4; np++) {
                    MMA16816(acc[mf][np * 2 + 0], aa[kk][mf], bb[kk][np][0], bb[kk][np][1]);
                    MMA16816(acc[mf][np * 2 + 1], aa[kk][mf], bb[kk][np][2], bb[kk][np][3]);
                }
    }

    // epilogue: add bias, direct stores
#pragma unroll
    for (int mf = 0; mf < 4; mf++) {
        const int r0 = m0 + mw * 64 + mf * 16 + (l >> 2);
#pragma unroll
        for (int nf = 0; nf < 8; nf++) {
            const int c  = n0 + nw * 64 + nf * 8 + ((l & 3) << 1);
            const float2 b2 = *(const float2*)&sbias[c - n0];
            float2 o0, o1;
            o0.x = acc[mf][nf][0] + b2.x;
            o0.y = acc[mf][nf][1] + b2.y;
            o1.x = acc[mf][nf][2] + b2.x;
            o1.y = acc[mf][nf][3] + b2.y;
            *(float2*)&out[(size_t)r0 * VOCAB + c]       = o0;
            *(float2*)&out[(size_t)(r0 + 8) * VOCAB + c] = o1;
        }
    }
}

// ---------------------------------------------------------------------------
extern "C" void kernel_launch(void* const* d_in, const int* in_sizes, int n_in,
                              void* d_out, int out_size)
{
    const float* enc_out  = (const float*)d_in[0];
    const float* pred_out = (const float*)d_in[1];
    const float* W_enc    = (const float*)d_in[2];
    const float* b_enc    = (const float*)d_in[3];
    const float* W_pred   = (const float*)d_in[4];
    const float* b_pred   = (const float*)d_in[5];
    const float* W_joint  = (const float*)d_in[6];
    const float* b_joint  = (const float*)d_in[7];
    float* out = (float*)d_out;

    static bool attr_done = false;
    if (!attr_done) {
        cudaFuncSetAttribute(joint_kernel, cudaFuncAttributeMaxDynamicSharedMemorySize, JOINT_SMEM);
        attr_done = true;
    }

    {
        dim3 grid(JDIM / 64, (BB * TT) / 64);   // 8 x 32 = 256 blocks
        proj_kernel<ENC_DIM, 0><<<grid, 256>>>(enc_out, W_enc, b_enc);
    }
    {
        dim3 grid(JDIM / 64, (BB * UU) / 64);   // 8 x 8 = 64 blocks
        proj_kernel<PRED_DIM, 1><<<grid, 256>>>(pred_out, W_pred, b_pred);
    }
    prep_w_kernel<<<(VOCAB * JDIM) / 256, 256>>>(W_joint);
    prep_a_kernel<<<((size_t)MROWS * JDIM / 16) / 256, 256>>>();
    joint_kernel<<<(MROWS / BM) * (VOCAB / BN), 256, JOINT_SMEM>>>(b_joint, out);
}

// round 9
// speedup vs baseline: 2.7503x; 1.0003x over previous
#include <cuda_runtime.h>
#include <cuda_fp16.h>
#include <cstdint>

#define BB 8
#define TT 256
#define UU 64
#define ENC_DIM 512
#define PRED_DIM 640
#define JDIM 512
#define VOCAB 1024
#define MROWS (BB * TT * UU)   // 131072

// ---------------------------------------------------------------------------
// Device scratch
// ---------------------------------------------------------------------------
__device__ float g_enc_p[BB * TT * JDIM];            // 4 MB
__device__ float g_pred_p[BB * UU * JDIM];           // 1 MB
__device__ __half g_a[(size_t)MROWS * JDIM];         // 128 MB (fp16 tanh plane)
__device__ __half g_wt[VOCAB * JDIM];                // 1 MB  (W^T fp16)

// ---------------------------------------------------------------------------
// Helpers
// ---------------------------------------------------------------------------
__device__ __forceinline__ uint32_t smem_u32(const void* p) {
    uint32_t a;
    asm("{ .reg .u64 t; cvta.to.shared.u64 t, %1; cvt.u32.u64 %0, t; }" : "=r"(a) : "l"(p));
    return a;
}
#define CP16(dst, src) \
    asm volatile("cp.async.cg.shared.global [%0], [%1], 16;" :: "r"((uint32_t)(dst)), "l"(src) : "memory")
#define CP_COMMIT() asm volatile("cp.async.commit_group;" ::: "memory")

#define LDSM4(r, addr) \
    asm volatile("ldmatrix.sync.aligned.m8n8.x4.shared.b16 {%0,%1,%2,%3}, [%4];" \
                 : "=r"((r)[0]), "=r"((r)[1]), "=r"((r)[2]), "=r"((r)[3]) : "r"(addr))

#define MMA16816(acc, a, b0, b1) \
    asm volatile("mma.sync.aligned.m16n8k16.row.col.f32.f16.f16.f32 " \
                 "{%0,%1,%2,%3},{%4,%5,%6,%7},{%8,%9},{%0,%1,%2,%3};" \
                 : "+f"((acc)[0]), "+f"((acc)[1]), "+f"((acc)[2]), "+f"((acc)[3]) \
                 : "r"((a)[0]), "r"((a)[1]), "r"((a)[2]), "r"((a)[3]), "r"(b0), "r"(b1))

// HW tanh (MUFU.TANH): ~2^-11 accuracy, matches fp16 quantization scale
__device__ __forceinline__ float tanh_hw(float x) {
    float y;
    asm("tanh.approx.f32 %0, %1;" : "=f"(y) : "f"(x));
    return y;
}
__device__ __forceinline__ uint32_t pack2h(__half a, __half b) {
    return (uint32_t)__half_as_ushort(a) | ((uint32_t)__half_as_ushort(b) << 16);
}

// ---------------------------------------------------------------------------
// Projection GEMM (fp32 SIMT): C[M, 512] = A[M, K] @ W[K, 512] + bias
// BM=64, BN=64, 256 threads, 4x4 microtile -> 256 blocks for enc (better occ)
// ---------------------------------------------------------------------------
template <int K, int WHICH>
__global__ __launch_bounds__(256) void proj_kernel(
    const float* __restrict__ A, const float* __restrict__ W, const float* __restrict__ bias)
{
    __shared__ float As[16][68];
    __shared__ float Bs[16][68];
    float* __restrict__ C = (WHICH == 0) ? g_enc_p : g_pred_p;
    const int N = JDIM;
    const int tid = threadIdx.x;
    const int ty = tid >> 4, tx = tid & 15;       // 16 x 16 thread grid
    const int m0 = blockIdx.y * 64, n0 = blockIdx.x * 64;
    const int lm = tid >> 2, lk = (tid & 3) << 2; // A loader
    const int bk = tid >> 4, bn = (tid & 15) << 2; // B loader

    float acc[4][4];
#pragma unroll
    for (int i = 0; i < 4; i++)
#pragma unroll
        for (int j = 0; j < 4; j++) acc[i][j] = 0.0f;

    for (int k0 = 0; k0 < K; k0 += 16) {
        float4 a4 = *(const float4*)&A[(m0 + lm) * K + k0 + lk];
        As[lk + 0][lm] = a4.x; As[lk + 1][lm] = a4.y;
        As[lk + 2][lm] = a4.z; As[lk + 3][lm] = a4.w;
        *(float4*)&Bs[bk][bn] = *(const float4*)&W[(k0 + bk) * N + n0 + bn];
        __syncthreads();
#pragma unroll
        for (int k = 0; k < 16; k++) {
            float4 av = *(const float4*)&As[k][ty << 2];
            float4 bv = *(const float4*)&Bs[k][tx << 2];
            float a[4] = {av.x, av.y, av.z, av.w};
            float b[4] = {bv.x, bv.y, bv.z, bv.w};
#pragma unroll
            for (int i = 0; i < 4; i++)
#pragma unroll
                for (int j = 0; j < 4; j++) acc[i][j] = fmaf(a[i], b[j], acc[i][j]);
        }
        __syncthreads();
    }
#pragma unroll
    for (int j = 0; j < 4; j++) {
        float bj = bias[n0 + (tx << 2) + j];
#pragma unroll
        for (int i = 0; i < 4; i++)
            C[(m0 + (ty << 2) + i) * N + n0 + (tx << 2) + j] = acc[i][j] + bj;
    }
}

// ---------------------------------------------------------------------------
// prep_W: Wt[v,k] = fp16(W_joint[k,v])
// ---------------------------------------------------------------------------
__global__ __launch_bounds__(256) void prep_w_kernel(const float* __restrict__ W) {
    int gid = blockIdx.x * 256 + threadIdx.x;       // 0 .. 524287
    int v = gid >> 9, k = gid & 511;
    g_wt[gid] = __float2half_rn(W[k * VOCAB + v]);
}

// ---------------------------------------------------------------------------
// prep_A: A[m,k] = fp16(tanh(enc_p[bt,k] + pred_p[b,u,k]))  (MUFU tanh)
// Each thread handles (bt, k8) for u and u+32 -> enc row load shared, MLP=6.
// ---------------------------------------------------------------------------
__global__ __launch_bounds__(256) void prep_a_kernel() {
    int gid = blockIdx.x * 256 + threadIdx.x;       // 0 .. 4194303
    int bt = gid >> 11;                 // 2048 threads per bt
    int r  = gid & 2047;
    int u  = r >> 6;                    // 0..31
    int k8 = (r & 63) << 3;
    int b  = bt >> 8;

    const float4* e  = (const float4*)(g_enc_p + (size_t)bt * JDIM + k8);
    const float4* p0 = (const float4*)(g_pred_p + ((size_t)(b * UU + u)) * JDIM + k8);
    const float4* p1 = (const float4*)(g_pred_p + ((size_t)(b * UU + u + 32)) * JDIM + k8);

    float4 e0 = e[0],  e1 = e[1];
    float4 pa = p0[0], pb = p0[1];
    float4 pc = p1[0], pd = p1[1];

    __half h0[8], h1[8];
    h0[0] = __float2half_rn(tanh_hw(e0.x + pa.x));
    h0[1] = __float2half_rn(tanh_hw(e0.y + pa.y));
    h0[2] = __float2half_rn(tanh_hw(e0.z + pa.z));
    h0[3] = __float2half_rn(tanh_hw(e0.w + pa.w));
    h0[4] = __float2half_rn(tanh_hw(e1.x + pb.x));
    h0[5] = __float2half_rn(tanh_hw(e1.y + pb.y));
    h0[6] = __float2half_rn(tanh_hw(e1.z + pb.z));
    h0[7] = __float2half_rn(tanh_hw(e1.w + pb.w));
    h1[0] = __float2half_rn(tanh_hw(e0.x + pc.x));
    h1[1] = __float2half_rn(tanh_hw(e0.y + pc.y));
    h1[2] = __float2half_rn(tanh_hw(e0.z + pc.z));
    h1[3] = __float2half_rn(tanh_hw(e0.w + pc.w));
    h1[4] = __float2half_rn(tanh_hw(e1.x + pd.x));
    h1[5] = __float2half_rn(tanh_hw(e1.y + pd.y));
    h1[6] = __float2half_rn(tanh_hw(e1.z + pd.z));
    h1[7] = __float2half_rn(tanh_hw(e1.w + pd.w));

    uint4 H0, H1;
    H0.x = pack2h(h0[0], h0[1]); H0.y = pack2h(h0[2], h0[3]);
    H0.z = pack2h(h0[4], h0[5]); H0.w = pack2h(h0[6], h0[7]);
    H1.x = pack2h(h1[0], h1[1]); H1.y = pack2h(h1[2], h1[3]);
    H1.z = pack2h(h1[4], h1[5]); H1.w = pack2h(h1[6], h1[7]);
    size_t m0 = (size_t)(bt * UU + u) * JDIM + k8;
    *(uint4*)(g_a + m0)                      = H0;
    *(uint4*)(g_a + m0 + (size_t)32 * JDIM)  = H1;
}

// ---------------------------------------------------------------------------
// Joint GEMM via mma.sync (HMMA): C = A_fp16 @ Wt_fp16^T + bias  (single pass)
// BM=128, BN=256, BK=64, 256 threads (8 warps 2x4), warp tile 64x64.
// 8 stages, NPIPE=3 cp.async pipeline; LDSM hoisted per kk-pair; half the
// barrier/wait overhead of the BK=32 version.
// ---------------------------------------------------------------------------
#define BM 128
#define BN 256
#define BK 64
#define NSTG 8                          // 512 / 64
#define NPIPE 3
#define ASTRIDE 144                     // 64 fp16 = 128B data, padded to 144B
#define A_PLANE (BM * ASTRIDE)          // 18432
#define B_PLANE (BN * ASTRIDE)          // 36864
#define STG_BYTES (A_PLANE + B_PLANE)   // 55296
#define OFF_A 0
#define OFF_B A_PLANE
#define JOINT_SMEM (NPIPE * STG_BYTES + 1024)  // 166912 (+bias)

__device__ __forceinline__ void load_stage(uint32_t sbase, int k0, int m0, int n0, int tid) {
#pragma unroll
    for (int it = 0; it < 4; it++) {
        int c = tid + it * 256;            // 0..1023
        int row = c >> 3, cq = c & 7;
        CP16(sbase + OFF_A + row * ASTRIDE + cq * 16,
             g_a + (size_t)(m0 + row) * JDIM + k0 + cq * 8);
    }
#pragma unroll
    for (int it = 0; it < 8; it++) {
        int c = tid + it * 256;            // 0..2047
        int row = c >> 3, cq = c & 7;
        CP16(sbase + OFF_B + row * ASTRIDE + cq * 16,
             g_wt + (size_t)(n0 + row) * JDIM + k0 + cq * 8);
    }
}

__global__ __launch_bounds__(256, 1) void joint_kernel(
    const float* __restrict__ bias, float* __restrict__ out)
{
    extern __shared__ char dsm[];
    const uint32_t sb = smem_u32(dsm);
    float* sbias = (float*)(dsm + NPIPE * STG_BYTES);

    const int tid = threadIdx.x;
    const int l   = tid & 31;
    const int w   = tid >> 5;
    const int mw  = w & 1;        // 0..1  -> 64-row slab
    const int nw  = w >> 1;       // 0..3  -> 64-col slab
    const int bid = blockIdx.x;
    const int n0  = (bid & 3) * BN;
    const int m0  = (bid >> 2) * BM;

    sbias[tid] = bias[n0 + tid];

    load_stage(sb + 0 * STG_BYTES, 0 * BK, m0, n0, tid); CP_COMMIT();
    load_stage(sb + 1 * STG_BYTES, 1 * BK, m0, n0, tid); CP_COMMIT();

    float acc[4][8][4];
#pragma unroll
    for (int i = 0; i < 4; i++)
#pragma unroll
        for (int j = 0; j < 8; j++)
#pragma unroll
            for (int q = 0; q < 4; q++) acc[i][j][q] = 0.0f;

    const uint32_t a_off = (uint32_t)((mw * 64 + (l & 15)) * ASTRIDE + (l >> 4) * 16);
    const uint32_t b_off = (uint32_t)((nw * 64 + ((l >> 4) << 3) + (l & 7)) * ASTRIDE
                                      + ((l >> 3) & 1) * 16);

    for (int s = 0; s < NSTG; s++) {
        // stage s resident (2 groups may be in flight; keep 1)
        asm volatile("cp.async.wait_group 1;" ::: "memory");
        __syncthreads();

        const uint32_t stg = sb + (s % NPIPE) * STG_BYTES;
        uint32_t aa[2][4][4], bb[2][4][4];

        // ---- kk-pair 0 (kk = 0,1) ----
#pragma unroll
        for (int kk = 0; kk < 2; kk++) {
#pragma unroll
            for (int mf = 0; mf < 4; mf++)
                LDSM4(aa[kk][mf], stg + OFF_A + a_off + kk * 32 + mf * 16 * ASTRIDE);
#pragma unroll
            for (int np = 0; np < 4; np++)
                LDSM4(bb[kk][np], stg + OFF_B + b_off + kk * 32 + np * 16 * ASTRIDE);
        }
        // prefetch stage s+2 in the LDSM/MMA shadow (uniform commit)
        if (s + 2 < NSTG)
            load_stage(sb + ((s + 2) % NPIPE) * STG_BYTES, (s + 2) * BK, m0, n0, tid);
        CP_COMMIT();
#pragma unroll
        for (int kk = 0; kk < 2; kk++)
#pragma unroll
            for (int mf = 0; mf < 4; mf++)
#pragma unroll
                for (int np = 0; np < 4; np++) {
                    MMA16816(acc[mf][np * 2 + 0], aa[kk][mf], bb[kk][np][0], bb[kk][np][1]);
                    MMA16816(acc[mf][np * 2 + 1], aa[kk][mf], bb[kk][np][2], bb[kk][np][3]);
                }

        // ---- kk-pair 1 (kk = 2,3), registers reused ----
#pragma unroll
        for (int kk = 0; kk < 2; kk++) {
#pragma unroll
            for (int mf = 0; mf < 4; mf++)
                LDSM4(aa[kk][mf], stg + OFF_A + a_off + 64 + kk * 32 + mf * 16 * ASTRIDE);
#pragma unroll
            for (int np = 0; np < 4; np++)
                LDSM4(bb[kk][np], stg + OFF_B + b_off + 64 + kk * 32 + np * 16 * ASTRIDE);
        }
#pragma unroll
        for (int kk = 0; kk < 2; kk++)
#pragma unroll
            for (int mf = 0; mf < 4; mf++)
#pragma unroll
                for (int np = 0; np < 4; np++) {
                    MMA16816(acc[mf][np * 2 + 0], aa[kk][mf], bb[kk][np][0], bb[kk][np][1]);
                    MMA16816(acc[mf][np * 2 + 1], aa[kk][mf], bb[kk][np][2], bb[kk][np][3]);
                }
    }

    // epilogue: add bias, direct stores
#pragma unroll
    for (int mf = 0; mf < 4; mf++) {
        const int r0 = m0 + mw * 64 + mf * 16 + (l >> 2);
#pragma unroll
        for (int nf = 0; nf < 8; nf++) {
            const int c  = n0 + nw * 64 + nf * 8 + ((l & 3) << 1);
            const float2 b2 = *(const float2*)&sbias[c - n0];
            float2 o0, o1;
            o0.x = acc[mf][nf][0] + b2.x;
            o0.y = acc[mf][nf][1] + b2.y;
            o1.x = acc[mf][nf][2] + b2.x;
            o1.y = acc[mf][nf][3] + b2.y;
            *(float2*)&out[(size_t)r0 * VOCAB + c]       = o0;
            *(float2*)&out[(size_t)(r0 + 8) * VOCAB + c] = o1;
        }
    }
}

// ---------------------------------------------------------------------------
extern "C" void kernel_launch(void* const* d_in, const int* in_sizes, int n_in,
                              void* d_out, int out_size)
{
    const float* enc_out  = (const float*)d_in[0];
    const float* pred_out = (const float*)d_in[1];
    const float* W_enc    = (const float*)d_in[2];
    const float* b_enc    = (const float*)d_in[3];
    const float* W_pred   = (const float*)d_in[4];
    const float* b_pred   = (const float*)d_in[5];
    const float* W_joint  = (const float*)d_in[6];
    const float* b_joint  = (const float*)d_in[7];
    float* out = (float*)d_out;

    static bool attr_done = false;
    if (!attr_done) {
        cudaFuncSetAttribute(joint_kernel, cudaFuncAttributeMaxDynamicSharedMemorySize, JOINT_SMEM);
        attr_done = true;
    }

    {
        dim3 grid(JDIM / 64, (BB * TT) / 64);   // 8 x 32 = 256 blocks
        proj_kernel<ENC_DIM, 0><<<grid, 256>>>(enc_out, W_enc, b_enc);
    }
    {
        dim3 grid(JDIM / 64, (BB * UU) / 64);   // 8 x 8 = 64 blocks
        proj_kernel<PRED_DIM, 1><<<grid, 256>>>(pred_out, W_pred, b_pred);
    }
    prep_w_kernel<<<(VOCAB * JDIM) / 256, 256>>>(W_joint);
    prep_a_kernel<<<((size_t)MROWS * JDIM / 16) / 256, 256>>>();
    joint_kernel<<<(MROWS / BM) * (VOCAB / BN), 256, JOINT_SMEM>>>(b_joint, out);
}

// round 10
// speedup vs baseline: 2.7596x; 1.0034x over previous
#include <cuda_runtime.h>
#include <cuda_fp16.h>
#include <cstdint>

#define BB 8
#define TT 256
#define UU 64
#define ENC_DIM 512
#define PRED_DIM 640
#define JDIM 512
#define VOCAB 1024
#define MROWS (BB * TT * UU)   // 131072

// ---------------------------------------------------------------------------
// Device scratch
// ---------------------------------------------------------------------------
__device__ float g_enc_p[BB * TT * JDIM];            // 4 MB
__device__ float g_pred_p[BB * UU * JDIM];           // 1 MB
__device__ __half g_a[(size_t)MROWS * JDIM];         // 128 MB (fp16 tanh plane)
__device__ __half g_wt[VOCAB * JDIM];                // 1 MB  (W^T fp16)

// ---------------------------------------------------------------------------
// Helpers
// ---------------------------------------------------------------------------
__device__ __forceinline__ uint32_t smem_u32(const void* p) {
    uint32_t a;
    asm("{ .reg .u64 t; cvta.to.shared.u64 t, %1; cvt.u32.u64 %0, t; }" : "=r"(a) : "l"(p));
    return a;
}
#define CP16(dst, src) \
    asm volatile("cp.async.cg.shared.global [%0], [%1], 16;" :: "r"((uint32_t)(dst)), "l"(src) : "memory")
#define CP_COMMIT() asm volatile("cp.async.commit_group;" ::: "memory")

#define LDSM4(r, addr) \
    asm volatile("ldmatrix.sync.aligned.m8n8.x4.shared.b16 {%0,%1,%2,%3}, [%4];" \
                 : "=r"((r)[0]), "=r"((r)[1]), "=r"((r)[2]), "=r"((r)[3]) : "r"(addr))

#define MMA16816(acc, a, b0, b1) \
    asm volatile("mma.sync.aligned.m16n8k16.row.col.f32.f16.f16.f32 " \
                 "{%0,%1,%2,%3},{%4,%5,%6,%7},{%8,%9},{%0,%1,%2,%3};" \
                 : "+f"((acc)[0]), "+f"((acc)[1]), "+f"((acc)[2]), "+f"((acc)[3]) \
                 : "r"((a)[0]), "r"((a)[1]), "r"((a)[2]), "r"((a)[3]), "r"(b0), "r"(b1))

// HW tanh (MUFU.TANH): ~2^-11 accuracy, matches fp16 quantization scale
__device__ __forceinline__ float tanh_hw(float x) {
    float y;
    asm("tanh.approx.f32 %0, %1;" : "=f"(y) : "f"(x));
    return y;
}
__device__ __forceinline__ uint32_t pack2h(__half a, __half b) {
    return (uint32_t)__half_as_ushort(a) | ((uint32_t)__half_as_ushort(b) << 16);
}

// ---------------------------------------------------------------------------
// Projection GEMM (fp32 SIMT): C[M, 512] = A[M, K] @ W[K, 512] + bias
// BM=64, BN=64, 256 threads, 4x4 microtile
// ---------------------------------------------------------------------------
template <int K, int WHICH>
__global__ __launch_bounds__(256) void proj_kernel(
    const float* __restrict__ A, const float* __restrict__ W, const float* __restrict__ bias)
{
    __shared__ float As[16][68];
    __shared__ float Bs[16][68];
    float* __restrict__ C = (WHICH == 0) ? g_enc_p : g_pred_p;
    const int N = JDIM;
    const int tid = threadIdx.x;
    const int ty = tid >> 4, tx = tid & 15;
    const int m0 = blockIdx.y * 64, n0 = blockIdx.x * 64;
    const int lm = tid >> 2, lk = (tid & 3) << 2;
    const int bk = tid >> 4, bn = (tid & 15) << 2;

    float acc[4][4];
#pragma unroll
    for (int i = 0; i < 4; i++)
#pragma unroll
        for (int j = 0; j < 4; j++) acc[i][j] = 0.0f;

    for (int k0 = 0; k0 < K; k0 += 16) {
        float4 a4 = *(const float4*)&A[(m0 + lm) * K + k0 + lk];
        As[lk + 0][lm] = a4.x; As[lk + 1][lm] = a4.y;
        As[lk + 2][lm] = a4.z; As[lk + 3][lm] = a4.w;
        *(float4*)&Bs[bk][bn] = *(const float4*)&W[(k0 + bk) * N + n0 + bn];
        __syncthreads();
#pragma unroll
        for (int k = 0; k < 16; k++) {
            float4 av = *(const float4*)&As[k][ty << 2];
            float4 bv = *(const float4*)&Bs[k][tx << 2];
            float a[4] = {av.x, av.y, av.z, av.w};
            float b[4] = {bv.x, bv.y, bv.z, bv.w};
#pragma unroll
            for (int i = 0; i < 4; i++)
#pragma unroll
                for (int j = 0; j < 4; j++) acc[i][j] = fmaf(a[i], b[j], acc[i][j]);
        }
        __syncthreads();
    }
#pragma unroll
    for (int j = 0; j < 4; j++) {
        float bj = bias[n0 + (tx << 2) + j];
#pragma unroll
        for (int i = 0; i < 4; i++)
            C[(m0 + (ty << 2) + i) * N + n0 + (tx << 2) + j] = acc[i][j] + bj;
    }
}

// ---------------------------------------------------------------------------
// prep_W: Wt[v,k] = fp16(W_joint[k,v])
// ---------------------------------------------------------------------------
__global__ __launch_bounds__(256) void prep_w_kernel(const float* __restrict__ W) {
    int gid = blockIdx.x * 256 + threadIdx.x;       // 0 .. 524287
    int v = gid >> 9, k = gid & 511;
    g_wt[gid] = __float2half_rn(W[k * VOCAB + v]);
}

// ---------------------------------------------------------------------------
// prep_A: A[m,k] = fp16(tanh(enc_p[bt,k] + pred_p[b,u,k]))  (MUFU tanh)
// Each thread handles (bt, k8) for u and u+32 -> enc row load shared.
// ---------------------------------------------------------------------------
__global__ __launch_bounds__(256) void prep_a_kernel() {
    int gid = blockIdx.x * 256 + threadIdx.x;       // 0 .. 4194303
    int bt = gid >> 11;
    int r  = gid & 2047;
    int u  = r >> 6;                    // 0..31
    int k8 = (r & 63) << 3;
    int b  = bt >> 8;

    const float4* e  = (const float4*)(g_enc_p + (size_t)bt * JDIM + k8);
    const float4* p0 = (const float4*)(g_pred_p + ((size_t)(b * UU + u)) * JDIM + k8);
    const float4* p1 = (const float4*)(g_pred_p + ((size_t)(b * UU + u + 32)) * JDIM + k8);

    float4 e0 = e[0],  e1 = e[1];
    float4 pa = p0[0], pb = p0[1];
    float4 pc = p1[0], pd = p1[1];

    __half h0[8], h1[8];
    h0[0] = __float2half_rn(tanh_hw(e0.x + pa.x));
    h0[1] = __float2half_rn(tanh_hw(e0.y + pa.y));
    h0[2] = __float2half_rn(tanh_hw(e0.z + pa.z));
    h0[3] = __float2half_rn(tanh_hw(e0.w + pa.w));
    h0[4] = __float2half_rn(tanh_hw(e1.x + pb.x));
    h0[5] = __float2half_rn(tanh_hw(e1.y + pb.y));
    h0[6] = __float2half_rn(tanh_hw(e1.z + pb.z));
    h0[7] = __float2half_rn(tanh_hw(e1.w + pb.w));
    h1[0] = __float2half_rn(tanh_hw(e0.x + pc.x));
    h1[1] = __float2half_rn(tanh_hw(e0.y + pc.y));
    h1[2] = __float2half_rn(tanh_hw(e0.z + pc.z));
    h1[3] = __float2half_rn(tanh_hw(e0.w + pc.w));
    h1[4] = __float2half_rn(tanh_hw(e1.x + pd.x));
    h1[5] = __float2half_rn(tanh_hw(e1.y + pd.y));
    h1[6] = __float2half_rn(tanh_hw(e1.z + pd.z));
    h1[7] = __float2half_rn(tanh_hw(e1.w + pd.w));

    uint4 H0, H1;
    H0.x = pack2h(h0[0], h0[1]); H0.y = pack2h(h0[2], h0[3]);
    H0.z = pack2h(h0[4], h0[5]); H0.w = pack2h(h0[6], h0[7]);
    H1.x = pack2h(h1[0], h1[1]); H1.y = pack2h(h1[2], h1[3]);
    H1.z = pack2h(h1[4], h1[5]); H1.w = pack2h(h1[6], h1[7]);
    size_t m0 = (size_t)(bt * UU + u) * JDIM + k8;
    *(uint4*)(g_a + m0)                      = H0;
    *(uint4*)(g_a + m0 + (size_t)32 * JDIM)  = H1;
}

// ---------------------------------------------------------------------------
// Joint GEMM via mma.sync (HMMA): C = A_fp16 @ Wt_fp16^T + bias  (single pass)
// BM=128, BN=128, BK=64, 256 threads (8 warps 2x4), warp tile 64x32.
// NPIPE=3 cp.async pipeline, 111.6 KB smem -> 2 blocks/SM: cross-block
// overlap hides per-stage bubbles and the epilogue drain.
// ---------------------------------------------------------------------------
#define BM 128
#define BN 128
#define BK 64
#define NSTG 8                          // 512 / 64
#define NPIPE 3
#define ASTRIDE 144                     // 64 fp16 = 128B data, padded to 144B
#define A_PLANE (BM * ASTRIDE)          // 18432
#define B_PLANE (BN * ASTRIDE)          // 18432
#define STG_BYTES (A_PLANE + B_PLANE)   // 36864
#define OFF_A 0
#define OFF_B A_PLANE
#define JOINT_SMEM (NPIPE * STG_BYTES + 1024)  // 111616 (+bias)

__device__ __forceinline__ void load_stage(uint32_t sbase, int k0, int m0, int n0, int tid) {
#pragma unroll
    for (int it = 0; it < 4; it++) {
        int c = tid + it * 256;            // 0..1023
        int row = c >> 3, cq = c & 7;
        CP16(sbase + OFF_A + row * ASTRIDE + cq * 16,
             g_a + (size_t)(m0 + row) * JDIM + k0 + cq * 8);
    }
#pragma unroll
    for (int it = 0; it < 4; it++) {
        int c = tid + it * 256;            // 0..1023
        int row = c >> 3, cq = c & 7;
        CP16(sbase + OFF_B + row * ASTRIDE + cq * 16,
             g_wt + (size_t)(n0 + row) * JDIM + k0 + cq * 8);
    }
}

__global__ __launch_bounds__(256, 2) void joint_kernel(
    const float* __restrict__ bias, float* __restrict__ out)
{
    extern __shared__ char dsm[];
    const uint32_t sb = smem_u32(dsm);
    float* sbias = (float*)(dsm + NPIPE * STG_BYTES);

    const int tid = threadIdx.x;
    const int l   = tid & 31;
    const int w   = tid >> 5;
    const int mw  = w & 1;        // 0..1  -> 64-row slab
    const int nw  = w >> 1;       // 0..3  -> 32-col slab
    const int bid = blockIdx.x;
    const int n0  = (bid & 7) * BN;     // n-major within m: co-resident N-blocks share A via L2
    const int m0  = (bid >> 3) * BM;

    if (tid < BN) sbias[tid] = bias[n0 + tid];

    load_stage(sb + 0 * STG_BYTES, 0 * BK, m0, n0, tid); CP_COMMIT();
    load_stage(sb + 1 * STG_BYTES, 1 * BK, m0, n0, tid); CP_COMMIT();

    float acc[4][4][4];
#pragma unroll
    for (int i = 0; i < 4; i++)
#pragma unroll
        for (int j = 0; j < 4; j++)
#pragma unroll
            for (int q = 0; q < 4; q++) acc[i][j][q] = 0.0f;

    const uint32_t a_off = (uint32_t)((mw * 64 + (l & 15)) * ASTRIDE + (l >> 4) * 16);
    const uint32_t b_off = (uint32_t)((nw * 32 + ((l >> 4) << 3) + (l & 7)) * ASTRIDE
                                      + ((l >> 3) & 1) * 16);

    for (int s = 0; s < NSTG; s++) {
        asm volatile("cp.async.wait_group 1;" ::: "memory");
        __syncthreads();

        const uint32_t stg = sb + (s % NPIPE) * STG_BYTES;
        uint32_t aa[2][4][4], bb[2][2][4];

        // ---- kk-pair 0 (kk = 0,1) ----
#pragma unroll
        for (int kk = 0; kk < 2; kk++) {
#pragma unroll
            for (int mf = 0; mf < 4; mf++)
                LDSM4(aa[kk][mf], stg + OFF_A + a_off + kk * 32 + mf * 16 * ASTRIDE);
#pragma unroll
            for (int np = 0; np < 2; np++)
                LDSM4(bb[kk][np], stg + OFF_B + b_off + kk * 32 + np * 16 * ASTRIDE);
        }
        // prefetch stage s+2 in the shadow (uniform commit)
        if (s + 2 < NSTG)
            load_stage(sb + ((s + 2) % NPIPE) * STG_BYTES, (s + 2) * BK, m0, n0, tid);
        CP_COMMIT();
#pragma unroll
        for (int kk = 0; kk < 2; kk++)
#pragma unroll
            for (int mf = 0; mf < 4; mf++)
#pragma unroll
                for (int np = 0; np < 2; np++) {
                    MMA16816(acc[mf][np * 2 + 0], aa[kk][mf], bb[kk][np][0], bb[kk][np][1]);
                    MMA16816(acc[mf][np * 2 + 1], aa[kk][mf], bb[kk][np][2], bb[kk][np][3]);
                }

        // ---- kk-pair 1 (kk = 2,3), registers reused ----
#pragma unroll
        for (int kk = 0; kk < 2; kk++) {
#pragma unroll
            for (int mf = 0; mf < 4; mf++)
                LDSM4(aa[kk][mf], stg + OFF_A + a_off + 64 + kk * 32 + mf * 16 * ASTRIDE);
#pragma unroll
            for (int np = 0; np < 2; np++)
                LDSM4(bb[kk][np], stg + OFF_B + b_off + 64 + kk * 32 + np * 16 * ASTRIDE);
        }
#pragma unroll
        for (int kk = 0; kk < 2; kk++)
#pragma unroll
            for (int mf = 0; mf < 4; mf++)
#pragma unroll
                for (int np = 0; np < 2; np++) {
                    MMA16816(acc[mf][np * 2 + 0], aa[kk][mf], bb[kk][np][0], bb[kk][np][1]);
                    MMA16816(acc[mf][np * 2 + 1], aa[kk][mf], bb[kk][np][2], bb[kk][np][3]);
                }
    }

    // epilogue: add bias, direct stores
#pragma unroll
    for (int mf = 0; mf < 4; mf++) {
        const int r0 = m0 + mw * 64 + mf * 16 + (l >> 2);
#pragma unroll
        for (int nf = 0; nf < 4; nf++) {
            const int c  = n0 + nw * 32 + nf * 8 + ((l & 3) << 1);
            const float2 b2 = *(const float2*)&sbias[c - n0];
            float2 o0, o1;
            o0.x = acc[mf][nf][0] + b2.x;
            o0.y = acc[mf][nf][1] + b2.y;
            o1.x = acc[mf][nf][2] + b2.x;
            o1.y = acc[mf][nf][3] + b2.y;
            *(float2*)&out[(size_t)r0 * VOCAB + c]       = o0;
            *(float2*)&out[(size_t)(r0 + 8) * VOCAB + c] = o1;
        }
    }
}

// ---------------------------------------------------------------------------
extern "C" void kernel_launch(void* const* d_in, const int* in_sizes, int n_in,
                              void* d_out, int out_size)
{
    const float* enc_out  = (const float*)d_in[0];
    const float* pred_out = (const float*)d_in[1];
    const float* W_enc    = (const float*)d_in[2];
    const float* b_enc    = (const float*)d_in[3];
    const float* W_pred   = (const float*)d_in[4];
    const float* b_pred   = (const float*)d_in[5];
    const float* W_joint  = (const float*)d_in[6];
    const float* b_joint  = (const float*)d_in[7];
    float* out = (float*)d_out;

    static bool attr_done = false;
    if (!attr_done) {
        cudaFuncSetAttribute(joint_kernel, cudaFuncAttributeMaxDynamicSharedMemorySize, JOINT_SMEM);
        attr_done = true;
    }

    {
        dim3 grid(JDIM / 64, (BB * TT) / 64);   // 256 blocks
        proj_kernel<ENC_DIM, 0><<<grid, 256>>>(enc_out, W_enc, b_enc);
    }
    {
        dim3 grid(JDIM / 64, (BB * UU) / 64);   // 64 blocks
        proj_kernel<PRED_DIM, 1><<<grid, 256>>>(pred_out, W_pred, b_pred);
    }
    prep_w_kernel<<<(VOCAB * JDIM) / 256, 256>>>(W_joint);
    prep_a_kernel<<<((size_t)MROWS * JDIM / 16) / 256, 256>>>();
    // 1024 m-tiles x 8 n-tiles, n-major within m
    joint_kernel<<<(MROWS / BM) * (VOCAB / BN), 256, JOINT_SMEM>>>(b_joint, out);
}